// round 12
// baseline (speedup 1.0000x reference)
#include <cuda_runtime.h>
#include <cuda_fp16.h>

#define T_SEQ 2048
#define BATCH 4
#define DIN   512
#define DOUT  256
#define NROWS 16384   // 2*BATCH*T_SEQ (q rows then k rows)

// Scratch (static __device__ — no allocation)
__device__ unsigned short g_X16[NROWS * DIN];   // fp16 q(rows 0-8191)|k(8192+)
__device__ unsigned short g_h1[NROWS * DOUT];   // fp16 hidden (a)
__device__ unsigned short g_h2[NROWS * DOUT];   // fp16 hidden (b)
__device__ unsigned short g_A[NROWS * DOUT];    // fp16 a-branch MLP out
__device__ unsigned short g_B[NROWS * DOUT];    // fp16 b-branch MLP out
// transposed fp16 weights [n][k]
__device__ unsigned short g_Wt1a[DOUT * DIN];
__device__ unsigned short g_Wt1b[DOUT * DIN];
__device__ unsigned short g_Wt2a[DOUT * DOUT];
__device__ unsigned short g_Wt2b[DOUT * DOUT];

// ---------------------------------------------------------------------------
// helpers
// ---------------------------------------------------------------------------
__device__ __forceinline__ float f_ex2(float x) {
    float y; asm("ex2.approx.ftz.f32 %0, %1;" : "=f"(y) : "f"(x)); return y;
}
__device__ __forceinline__ float f_lg2(float x) {
    float y; asm("lg2.approx.ftz.f32 %0, %1;" : "=f"(y) : "f"(x)); return y;
}
__device__ __forceinline__ float f_rcp(float x) {
    float y; asm("rcp.approx.ftz.f32 %0, %1;" : "=f"(y) : "f"(x)); return y;
}
__device__ __forceinline__ void mma_f16(
    float& c0, float& c1, float& c2, float& c3,
    unsigned a0, unsigned a1, unsigned a2, unsigned a3,
    unsigned b0, unsigned b1)
{
    asm("mma.sync.aligned.m16n8k16.row.col.f32.f16.f16.f32 "
        "{%0,%1,%2,%3}, {%4,%5,%6,%7}, {%8,%9}, {%0,%1,%2,%3};"
        : "+f"(c0), "+f"(c1), "+f"(c2), "+f"(c3)
        : "r"(a0), "r"(a1), "r"(a2), "r"(a3), "r"(b0), "r"(b1));
}
__device__ __forceinline__ void ldsm_x4(unsigned& r0, unsigned& r1,
                                        unsigned& r2, unsigned& r3, unsigned a) {
    asm volatile("ldmatrix.sync.aligned.m8n8.x4.shared.b16 {%0,%1,%2,%3}, [%4];"
                 : "=r"(r0), "=r"(r1), "=r"(r2), "=r"(r3) : "r"(a));
}
__device__ __forceinline__ void cp16(void* d, const void* s) {
    unsigned a = (unsigned)__cvta_generic_to_shared(d);
    asm volatile("cp.async.cg.shared.global [%0], [%1], 16;" :: "r"(a), "l"(s));
}
__device__ __forceinline__ void cp_commit() {
    asm volatile("cp.async.commit_group;");
}
template<int N> __device__ __forceinline__ void cp_wait() {
    asm volatile("cp.async.wait_group %0;" :: "n"(N));
}

#define LN2   0.69314718056f
#define RLN2  1.44269504089f

__device__ __forceinline__ float softplus_fast(float x) {
    float e = f_ex2(-fabsf(x) * RLN2);
    return fmaxf(x, 0.f) + f_lg2(1.f + e) * LN2;
}

// HardKuma epilogue, fused-Stirling Beta
__device__ __forceinline__ float kuma_out(float ar, float br) {
    const float K_T0 = -3.58496250072f;   // log2(1/12)
    const float K_T1 = -0.12553088208f;   // log2(11/12)
    float a  = fminf(fmaxf(softplus_fast(ar), 0.01f), 100.f);
    float bb = fminf(fmaxf(softplus_fast(br), 0.01f), 100.f);
    float u0 = f_ex2(a * K_T0);
    float u1 = f_ex2(a * K_T1);
    float E0 = f_ex2(bb * f_lg2(1.f - u0));  // 1 - p0
    float p1 = f_ex2(bb * f_lg2(1.f - u1));
    float pc = E0 - p1;

    float g  = 1.f + f_rcp(a);
    float s  = g + bb;
    float y1 = g + 4.f, y2 = bb + 4.f, y3 = s + 4.f;
    float L1 = f_lg2(y1), L2 = f_lg2(y2), L3 = f_lg2(y3);
    float pg = g  * (g  + 1.f) * (g  + 2.f) * (g  + 3.f);
    float pb = bb * (bb + 1.f) * (bb + 2.f) * (bb + 3.f);
    float ps = s  * (s  + 1.f) * (s  + 2.f) * (s  + 3.f);
    float pgb = pg * pb;
    float d3  = y1 * y2 * y3;
    float inv = f_rcp(d3 * pgb);
    float n   = fmaf(y1, y3, fmaf(y2, y3, -y1 * y2));
    float c   = 0.08333333333f * (n * pgb) * inv;
    float R   = ps * d3 * inv;
    float lm2 = (y1 - 0.5f) * L1 + (y2 - 0.5f) * L2 - (y3 - 0.5f) * L3
              + (c - 3.08106146679f) * RLN2;
    float mean = bb * R * f_ex2(lm2);
    mean = fminf(fmaxf(fmaf(1.2f, mean, -0.1f), 0.f), 1.f);

    float zo = (1.f - E0 > p1) ? 0.f : 1.f;
    return (pc < 0.5f) ? zo : mean;
}

// ---------------------------------------------------------------------------
// Prep kernel: blocks [0,4096) convert q,k fp32->fp16; blocks [4096,4608)
// transpose+convert the 4 weight matrices into [n][k] fp16.
// ---------------------------------------------------------------------------
#define QK_ELEMS (NROWS * DIN)   // 8.4M
#define CVT_BLOCKS (QK_ELEMS / 2048)   // 4096

__global__ void prep_kernel(
    const float* __restrict__ q,  const float* __restrict__ k, __half* __restrict__ X,
    const float* __restrict__ Wa1, const float* __restrict__ Wb1,
    const float* __restrict__ Wa2, const float* __restrict__ Wb2,
    __half* __restrict__ T1a, __half* __restrict__ T1b,
    __half* __restrict__ T2a, __half* __restrict__ T2b)
{
    int tid = threadIdx.x;
    if (blockIdx.x < CVT_BLOCKS) {
        long i = ((long)blockIdx.x * 256 + tid) * 8;
        const long half_pt = (long)(NROWS / 2) * DIN;
        const float* src = (i < half_pt) ? q + i : k + (i - half_pt);
        float4 v0 = *(const float4*)(src);
        float4 v1 = *(const float4*)(src + 4);
        __half2 h[4];
        h[0] = __floats2half2_rn(v0.x, v0.y);
        h[1] = __floats2half2_rn(v0.z, v0.w);
        h[2] = __floats2half2_rn(v1.x, v1.y);
        h[3] = __floats2half2_rn(v1.z, v1.w);
        *(uint4*)(X + i) = *(uint4*)h;
        return;
    }
    __shared__ float t[32][33];
    int idx = blockIdx.x - CVT_BLOCKS;    // [0, 512)
    int z  = idx >> 7;
    int rem = idx & 127;
    int gy = rem >> 4, gx = rem & 15;
    int K = (z < 2) ? DIN : DOUT;
    if (gx * 32 >= K) return;
    const float* S = (z == 0) ? Wa1 : (z == 1) ? Wb1 : (z == 2) ? Wa2 : Wb2;
    __half*      D = (z == 0) ? T1a : (z == 1) ? T1b : (z == 2) ? T2a : T2b;

    int kb = gx * 32, nb = gy * 32;
    int x = tid & 31, y = tid >> 5;  // 32 x 8
#pragma unroll
    for (int i = 0; i < 32; i += 8)
        t[y + i][x] = S[(long)(kb + y + i) * DOUT + nb + x];
    __syncthreads();
#pragma unroll
    for (int i = 0; i < 32; i += 8)
        D[(long)(nb + y + i) * K + kb + x] = __float2half(t[x][y + i]);
}

// ---------------------------------------------------------------------------
// fp16 MLP GEMM, cp.async 4-stage, BK=32 halfs, ldmatrix + mma.m16n8k16.
// C[16384,256] = fp16(relu(X @ W + bias)), dual weight set, W transposed.
// grid = (4, 128): x = set*2 + colblock(128). Block tile 128x128.
// 8 warps as 2(m)x4(n), warp tile 64x32. smem rows 80B (20 u32).
// ---------------------------------------------------------------------------
#define MLPH_TILE_U32 2560    // 128 rows x 20 u32
#define MLPH_SMEM_BYTES (4 * 2 * MLPH_TILE_U32 * 4)   // 81920

__global__ void __launch_bounds__(256, 2) mlp_f16_kernel(
    const __half* __restrict__ X1, const __half* __restrict__ Wt1,
    const float* __restrict__ bias1, __half* __restrict__ C1,
    const __half* __restrict__ X2, const __half* __restrict__ Wt2,
    const float* __restrict__ bias2, __half* __restrict__ C2,
    int K)
{
    extern __shared__ unsigned sm[];
    unsigned* ASb = sm;                        // 4 x 2560
    unsigned* BSb = sm + 4 * MLPH_TILE_U32;    // 4 x 2560

    int set = blockIdx.x >> 1;
    int bn  = blockIdx.x & 1;
    long rbase = (long)blockIdx.y * 128;

    const __half* X    = (set ? X2 : X1) + rbase * K;
    const __half* Wb   = (set ? Wt2 : Wt1) + (long)(bn * 128) * K;
    const float*  bias = set ? bias2 : bias1;
    __half*       C    = set ? C2  : C1;

    int tid = threadIdx.x;
    int wid = tid >> 5, lane = tid & 31;
    int wm  = wid >> 2, wn = wid & 3;          // 2(m) x 4(n)
    int g   = lane >> 2, t4 = lane & 3;

    int r0 = tid >> 2,          c0 = tid & 3;
    int r1 = (tid + 256) >> 2,  c1 = (tid + 256) & 3;

    int l7 = lane & 7, l8 = (lane >> 3) & 1, l16 = (lane >> 4) & 1;
    unsigned aoff = (unsigned)((wm * 64 + l7 + l8 * 8) * 80 + l16 * 16);  // +mt*1280
    unsigned boff = (unsigned)((wn * 32 + l7 + l16 * 8) * 80 + l8 * 16);  // +ntp*1280
    unsigned aBase = (unsigned)__cvta_generic_to_shared(ASb);
    unsigned bBase = (unsigned)__cvta_generic_to_shared(BSb);

    float acc[4][4][4];
#pragma unroll
    for (int mt = 0; mt < 4; mt++)
#pragma unroll
        for (int nt = 0; nt < 4; nt++)
#pragma unroll
            for (int c = 0; c < 4; c++) acc[mt][nt][c] = 0.f;

    const int ITERS = K >> 5;

#define MLP_ISSUE(ki) do {                                                    \
        int st_ = (ki) & 3; int k0_ = (ki) << 5;                              \
        unsigned* A_ = ASb + st_ * MLPH_TILE_U32;                             \
        unsigned* B_ = BSb + st_ * MLPH_TILE_U32;                             \
        cp16(A_ + r0 * 20 + c0 * 4, X  + (long)r0 * K + k0_ + c0 * 8);        \
        cp16(A_ + r1 * 20 + c1 * 4, X  + (long)r1 * K + k0_ + c1 * 8);        \
        cp16(B_ + r0 * 20 + c0 * 4, Wb + (long)r0 * K + k0_ + c0 * 8);        \
        cp16(B_ + r1 * 20 + c1 * 4, Wb + (long)r1 * K + k0_ + c1 * 8);        \
    } while (0)

    MLP_ISSUE(0); cp_commit();
    MLP_ISSUE(1); cp_commit();
    MLP_ISSUE(2); cp_commit();

    for (int it = 0; it < ITERS; it++) {
        cp_wait<2>();
        __syncthreads();
        if (it + 3 < ITERS) MLP_ISSUE(it + 3);
        cp_commit();

        int st = it & 3;
        unsigned aS = aBase + st * (MLPH_TILE_U32 * 4);
        unsigned bS = bBase + st * (MLPH_TILE_U32 * 4);

#pragma unroll
        for (int k16 = 0; k16 < 2; k16++) {
            unsigned kbyt = k16 * 32;
            unsigned af[4][4], bf[2][4];
#pragma unroll
            for (int mt = 0; mt < 4; mt++)
                ldsm_x4(af[mt][0], af[mt][1], af[mt][2], af[mt][3],
                        aS + aoff + mt * 1280 + kbyt);
#pragma unroll
            for (int ntp = 0; ntp < 2; ntp++)
                ldsm_x4(bf[ntp][0], bf[ntp][1], bf[ntp][2], bf[ntp][3],
                        bS + boff + ntp * 1280 + kbyt);
#pragma unroll
            for (int nt = 0; nt < 4; nt++) {
                unsigned b0 = bf[nt >> 1][(nt & 1) * 2];
                unsigned b1 = bf[nt >> 1][(nt & 1) * 2 + 1];
#pragma unroll
                for (int mt = 0; mt < 4; mt++)
                    mma_f16(acc[mt][nt][0], acc[mt][nt][1],
                            acc[mt][nt][2], acc[mt][nt][3],
                            af[mt][0], af[mt][1], af[mt][2], af[mt][3],
                            b0, b1);
            }
        }
    }

    // epilogue: bias + relu, fp16 out
#pragma unroll
    for (int mt = 0; mt < 4; mt++) {
#pragma unroll
        for (int rr = 0; rr < 2; rr++) {
            long row = rbase + wm * 64 + mt * 16 + g + rr * 8;
#pragma unroll
            for (int nt = 0; nt < 4; nt++) {
                int col = bn * 128 + wn * 32 + nt * 8 + t4 * 2;
                float ox = fmaxf(acc[mt][nt][rr*2+0] + bias[col    ], 0.f);
                float oy = fmaxf(acc[mt][nt][rr*2+1] + bias[col + 1], 0.f);
                *(__half2*)(C + row * DOUT + col) = __floats2half2_rn(ox, oy);
            }
        }
    }
}

// ---------------------------------------------------------------------------
// fp16 fused score GEMM (a & b) + HardKuma epilogue.
// 64x64 tile, 128 threads (4 warps as 2x2, warp 32x32), 3 blocks/SM for
// phase diversity (tensor GEMM of one block overlaps MUFU epilogue of
// another). cp.async 3-stage, BK=32 halfs, K=256 -> 8 iters.
// grid = (32, 32, 4).
// ---------------------------------------------------------------------------
#define T_TILE_U32 1280   // 64 rows x 20 u32
#define ATTN_SMEM_BYTES (3 * 4 * T_TILE_U32 * 4)   // 61440

__global__ void __launch_bounds__(128, 3) kuma_attn_f16_kernel(
    const unsigned short* __restrict__ Au, const unsigned short* __restrict__ Bu,
    const float* __restrict__ dist_emb, float* __restrict__ out)
{
    extern __shared__ unsigned sm[];
    unsigned* QAb = sm;                       // 3 x 1280
    unsigned* QBb = sm + 3 * T_TILE_U32;
    unsigned* KAb = sm + 6 * T_TILE_U32;
    unsigned* KBb = sm + 9 * T_TILE_U32;
    __shared__ float sdist[23];

    const __half* Ah = (const __half*)Au;
    const __half* Bh = (const __half*)Bu;

    int b  = blockIdx.z;
    int bt = blockIdx.y * 64;
    int bs = blockIdx.x * 64;
    int tid = threadIdx.x;
    if (tid < 23) sdist[tid] = dist_emb[tid];

    int wid = tid >> 5, lane = tid & 31;
    int wm  = wid >> 1, wn = wid & 1;     // 2(m) x 2(n)
    int g   = lane >> 2, t4 = lane & 3;

    const __half* qa = Ah + ((long)b * T_SEQ + bt) * DOUT;
    const __half* ka = Ah + ((long)(8192 + b * T_SEQ) + bs) * DOUT;
    const __half* qb = Bh + ((long)b * T_SEQ + bt) * DOUT;
    const __half* kb = Bh + ((long)(8192 + b * T_SEQ) + bs) * DOUT;

    // copy coords: 64 rows x 4 chunks(16B) = 256 per tile, 2/thread
    int r0 = tid >> 2,          c0 = tid & 3;
    int r1 = (tid + 128) >> 2,  c1 = (tid + 128) & 3;

    int l7 = lane & 7, l8 = (lane >> 3) & 1, l16 = (lane >> 4) & 1;
    unsigned aoff = (unsigned)((wm * 32 + l7 + l8 * 8) * 80 + l16 * 16);   // +mt*1280
    unsigned boff = (unsigned)((wn * 32 + l7 + l16 * 8) * 80 + l8 * 16);   // +ntp*1280
    unsigned qaB = (unsigned)__cvta_generic_to_shared(QAb);
    unsigned qbB = (unsigned)__cvta_generic_to_shared(QBb);
    unsigned kaB = (unsigned)__cvta_generic_to_shared(KAb);
    unsigned kbB = (unsigned)__cvta_generic_to_shared(KBb);

    float accA[2][4][4], accB[2][4][4];
#pragma unroll
    for (int mt = 0; mt < 2; mt++)
#pragma unroll
        for (int nt = 0; nt < 4; nt++)
#pragma unroll
            for (int c = 0; c < 4; c++) { accA[mt][nt][c] = 0.f; accB[mt][nt][c] = 0.f; }

    const int ITERS = DOUT >> 5;   // 8

#define ATTN_ISSUE(ki) do {                                                   \
        int st_ = (ki) % 3; int k0_ = (ki) << 5;                              \
        unsigned* QA_ = QAb + st_ * T_TILE_U32;                               \
        unsigned* QB_ = QBb + st_ * T_TILE_U32;                               \
        unsigned* KA_ = KAb + st_ * T_TILE_U32;                               \
        unsigned* KB_ = KBb + st_ * T_TILE_U32;                               \
        cp16(QA_ + r0 * 20 + c0 * 4, qa + (long)r0 * DOUT + k0_ + c0 * 8);    \
        cp16(QA_ + r1 * 20 + c1 * 4, qa + (long)r1 * DOUT + k0_ + c1 * 8);    \
        cp16(QB_ + r0 * 20 + c0 * 4, qb + (long)r0 * DOUT + k0_ + c0 * 8);    \
        cp16(QB_ + r1 * 20 + c1 * 4, qb + (long)r1 * DOUT + k0_ + c1 * 8);    \
        cp16(KA_ + r0 * 20 + c0 * 4, ka + (long)r0 * DOUT + k0_ + c0 * 8);    \
        cp16(KA_ + r1 * 20 + c1 * 4, ka + (long)r1 * DOUT + k0_ + c1 * 8);    \
        cp16(KB_ + r0 * 20 + c0 * 4, kb + (long)r0 * DOUT + k0_ + c0 * 8);    \
        cp16(KB_ + r1 * 20 + c1 * 4, kb + (long)r1 * DOUT + k0_ + c1 * 8);    \
    } while (0)

    ATTN_ISSUE(0); cp_commit();
    ATTN_ISSUE(1); cp_commit();

    for (int it = 0; it < ITERS; it++) {
        cp_wait<1>();
        __syncthreads();
        if (it + 2 < ITERS) ATTN_ISSUE(it + 2);
        cp_commit();

        int st = it % 3;
        unsigned qaS = qaB + st * (T_TILE_U32 * 4);
        unsigned qbS = qbB + st * (T_TILE_U32 * 4);
        unsigned kaS = kaB + st * (T_TILE_U32 * 4);
        unsigned kbS = kbB + st * (T_TILE_U32 * 4);

#pragma unroll
        for (int k16 = 0; k16 < 2; k16++) {
            unsigned kbyt = k16 * 32;
            unsigned qaf[2][4], qbf[2][4], kaf[2][4], kbf[2][4];
#pragma unroll
            for (int mt = 0; mt < 2; mt++) {
                ldsm_x4(qaf[mt][0], qaf[mt][1], qaf[mt][2], qaf[mt][3],
                        qaS + aoff + mt * 1280 + kbyt);
                ldsm_x4(qbf[mt][0], qbf[mt][1], qbf[mt][2], qbf[mt][3],
                        qbS + aoff + mt * 1280 + kbyt);
            }
#pragma unroll
            for (int ntp = 0; ntp < 2; ntp++) {
                ldsm_x4(kaf[ntp][0], kaf[ntp][1], kaf[ntp][2], kaf[ntp][3],
                        kaS + boff + ntp * 1280 + kbyt);
                ldsm_x4(kbf[ntp][0], kbf[ntp][1], kbf[ntp][2], kbf[ntp][3],
                        kbS + boff + ntp * 1280 + kbyt);
            }
#pragma unroll
            for (int nt = 0; nt < 4; nt++) {
                unsigned bA0 = kaf[nt >> 1][(nt & 1) * 2];
                unsigned bA1 = kaf[nt >> 1][(nt & 1) * 2 + 1];
                unsigned bB0 = kbf[nt >> 1][(nt & 1) * 2];
                unsigned bB1 = kbf[nt >> 1][(nt & 1) * 2 + 1];
#pragma unroll
                for (int mt = 0; mt < 2; mt++) {
                    mma_f16(accA[mt][nt][0], accA[mt][nt][1],
                            accA[mt][nt][2], accA[mt][nt][3],
                            qaf[mt][0], qaf[mt][1], qaf[mt][2], qaf[mt][3],
                            bA0, bA1);
                    mma_f16(accB[mt][nt][0], accB[mt][nt][1],
                            accB[mt][nt][2], accB[mt][nt][3],
                            qbf[mt][0], qbf[mt][1], qbf[mt][2], qbf[mt][3],
                            bB0, bB1);
                }
            }
        }
    }

    // HardKuma epilogue + store
#pragma unroll
    for (int mt = 0; mt < 2; mt++) {
#pragma unroll
        for (int rr = 0; rr < 2; rr++) {
            int trow = bt + wm * 32 + mt * 16 + g + rr * 8;
#pragma unroll
            for (int nt = 0; nt < 4; nt++) {
                int scol = bs + wn * 32 + nt * 8 + t4 * 2;
                int rel0 = max(-11, min(11, scol     - trow)) + 11;
                int rel1 = max(-11, min(11, scol + 1 - trow)) + 11;
                float rd0 = sdist[rel0], rd1 = sdist[rel1];
                float2 o;
                o.x = kuma_out(accA[mt][nt][rr*2+0] + rd0, accB[mt][nt][rr*2+0] + rd0);
                o.y = kuma_out(accA[mt][nt][rr*2+1] + rd1, accB[mt][nt][rr*2+1] + rd1);
                *(float2*)(out + ((long)b * T_SEQ + trow) * T_SEQ + scol) = o;
            }
        }
    }
}

// ---------------------------------------------------------------------------
extern "C" void kernel_launch(void* const* d_in, const int* in_sizes, int n_in,
                              void* d_out, int out_size)
{
    const float* q    = (const float*)d_in[0];
    const float* k    = (const float*)d_in[1];
    const float* Wa1  = (const float*)d_in[2];
    const float* ba1  = (const float*)d_in[3];
    const float* Wa2  = (const float*)d_in[4];
    const float* ba2  = (const float*)d_in[5];
    const float* Wb1  = (const float*)d_in[6];
    const float* bb1  = (const float*)d_in[7];
    const float* Wb2  = (const float*)d_in[8];
    const float* bb2  = (const float*)d_in[9];
    const float* dist = (const float*)d_in[10];
    float* out = (float*)d_out;

    unsigned short *X16, *h1, *h2, *Ah, *Bh, *t1a, *t1b, *t2a, *t2b;
    cudaGetSymbolAddress((void**)&X16, g_X16);
    cudaGetSymbolAddress((void**)&h1,  g_h1);
    cudaGetSymbolAddress((void**)&h2,  g_h2);
    cudaGetSymbolAddress((void**)&Ah,  g_A);
    cudaGetSymbolAddress((void**)&Bh,  g_B);
    cudaGetSymbolAddress((void**)&t1a, g_Wt1a);
    cudaGetSymbolAddress((void**)&t1b, g_Wt1b);
    cudaGetSymbolAddress((void**)&t2a, g_Wt2a);
    cudaGetSymbolAddress((void**)&t2b, g_Wt2b);

    cudaFuncSetAttribute(mlp_f16_kernel,
        cudaFuncAttributeMaxDynamicSharedMemorySize, MLPH_SMEM_BYTES);
    cudaFuncSetAttribute(kuma_attn_f16_kernel,
        cudaFuncAttributeMaxDynamicSharedMemorySize, ATTN_SMEM_BYTES);

    prep_kernel<<<CVT_BLOCKS + 512, 256>>>(
        q, k, (__half*)X16,
        Wa1, Wb1, Wa2, Wb2,
        (__half*)t1a, (__half*)t1b, (__half*)t2a, (__half*)t2b);

    dim3 g1(4, 128);
    mlp_f16_kernel<<<g1, 256, MLPH_SMEM_BYTES>>>(
        (const __half*)X16, (const __half*)t1a, ba1, (__half*)h1,
        (const __half*)X16, (const __half*)t1b, bb1, (__half*)h2, DIN);
    mlp_f16_kernel<<<g1, 256, MLPH_SMEM_BYTES>>>(
        (const __half*)h1, (const __half*)t2a, ba2, (__half*)Ah,
        (const __half*)h2, (const __half*)t2b, bb2, (__half*)Bh, DOUT);

    dim3 g2(T_SEQ / 64, T_SEQ / 64, BATCH);
    kuma_attn_f16_kernel<<<g2, 128, ATTN_SMEM_BYTES>>>(Ah, Bh, dist, out);
}

// round 13
// speedup vs baseline: 1.0648x; 1.0648x over previous
#include <cuda_runtime.h>
#include <cuda_fp16.h>

#define T_SEQ 2048
#define BATCH 4
#define DIN   512
#define DOUT  256
#define NROWS 16384   // 2*BATCH*T_SEQ (q rows then k rows)

// Scratch (static __device__ — no allocation)
__device__ unsigned short g_X16[NROWS * DIN];   // fp16 q(rows 0-8191)|k(8192+)
__device__ unsigned short g_h1[NROWS * DOUT];   // fp16 hidden (a)
__device__ unsigned short g_h2[NROWS * DOUT];   // fp16 hidden (b)
__device__ unsigned short g_A[NROWS * DOUT];    // fp16 a-branch MLP out
__device__ unsigned short g_B[NROWS * DOUT];    // fp16 b-branch MLP out
// transposed fp16 weights [n][k]
__device__ unsigned short g_Wt1a[DOUT * DIN];
__device__ unsigned short g_Wt1b[DOUT * DIN];
__device__ unsigned short g_Wt2a[DOUT * DOUT];
__device__ unsigned short g_Wt2b[DOUT * DOUT];

// ---------------------------------------------------------------------------
// helpers
// ---------------------------------------------------------------------------
__device__ __forceinline__ float f_ex2(float x) {
    float y; asm("ex2.approx.ftz.f32 %0, %1;" : "=f"(y) : "f"(x)); return y;
}
__device__ __forceinline__ float f_lg2(float x) {
    float y; asm("lg2.approx.ftz.f32 %0, %1;" : "=f"(y) : "f"(x)); return y;
}
__device__ __forceinline__ float f_rcp(float x) {
    float y; asm("rcp.approx.ftz.f32 %0, %1;" : "=f"(y) : "f"(x)); return y;
}
__device__ __forceinline__ void mma_f16(
    float& c0, float& c1, float& c2, float& c3,
    unsigned a0, unsigned a1, unsigned a2, unsigned a3,
    unsigned b0, unsigned b1)
{
    asm("mma.sync.aligned.m16n8k16.row.col.f32.f16.f16.f32 "
        "{%0,%1,%2,%3}, {%4,%5,%6,%7}, {%8,%9}, {%0,%1,%2,%3};"
        : "+f"(c0), "+f"(c1), "+f"(c2), "+f"(c3)
        : "r"(a0), "r"(a1), "r"(a2), "r"(a3), "r"(b0), "r"(b1));
}
__device__ __forceinline__ void ldsm_x4(unsigned& r0, unsigned& r1,
                                        unsigned& r2, unsigned& r3, unsigned a) {
    asm volatile("ldmatrix.sync.aligned.m8n8.x4.shared.b16 {%0,%1,%2,%3}, [%4];"
                 : "=r"(r0), "=r"(r1), "=r"(r2), "=r"(r3) : "r"(a));
}
__device__ __forceinline__ void cp16(void* d, const void* s) {
    unsigned a = (unsigned)__cvta_generic_to_shared(d);
    asm volatile("cp.async.cg.shared.global [%0], [%1], 16;" :: "r"(a), "l"(s));
}
__device__ __forceinline__ void cp_commit() {
    asm volatile("cp.async.commit_group;");
}
template<int N> __device__ __forceinline__ void cp_wait() {
    asm volatile("cp.async.wait_group %0;" :: "n"(N));
}

#define LN2   0.69314718056f
#define RLN2  1.44269504089f

__device__ __forceinline__ float softplus_fast(float x) {
    float e = f_ex2(-fabsf(x) * RLN2);
    return fmaxf(x, 0.f) + f_lg2(1.f + e) * LN2;
}

// HardKuma epilogue, fused-Stirling Beta
__device__ __forceinline__ float kuma_out(float ar, float br) {
    const float K_T0 = -3.58496250072f;   // log2(1/12)
    const float K_T1 = -0.12553088208f;   // log2(11/12)
    float a  = fminf(fmaxf(softplus_fast(ar), 0.01f), 100.f);
    float bb = fminf(fmaxf(softplus_fast(br), 0.01f), 100.f);
    float u0 = f_ex2(a * K_T0);
    float u1 = f_ex2(a * K_T1);
    float E0 = f_ex2(bb * f_lg2(1.f - u0));  // 1 - p0
    float p1 = f_ex2(bb * f_lg2(1.f - u1));
    float pc = E0 - p1;

    float g  = 1.f + f_rcp(a);
    float s  = g + bb;
    float y1 = g + 4.f, y2 = bb + 4.f, y3 = s + 4.f;
    float L1 = f_lg2(y1), L2 = f_lg2(y2), L3 = f_lg2(y3);
    float pg = g  * (g  + 1.f) * (g  + 2.f) * (g  + 3.f);
    float pb = bb * (bb + 1.f) * (bb + 2.f) * (bb + 3.f);
    float ps = s  * (s  + 1.f) * (s  + 2.f) * (s  + 3.f);
    float pgb = pg * pb;
    float d3  = y1 * y2 * y3;
    float inv = f_rcp(d3 * pgb);
    float n   = fmaf(y1, y3, fmaf(y2, y3, -y1 * y2));
    float c   = 0.08333333333f * (n * pgb) * inv;
    float R   = ps * d3 * inv;
    float lm2 = (y1 - 0.5f) * L1 + (y2 - 0.5f) * L2 - (y3 - 0.5f) * L3
              + (c - 3.08106146679f) * RLN2;
    float mean = bb * R * f_ex2(lm2);
    mean = fminf(fmaxf(fmaf(1.2f, mean, -0.1f), 0.f), 1.f);

    float zo = (1.f - E0 > p1) ? 0.f : 1.f;
    return (pc < 0.5f) ? zo : mean;
}

// ---------------------------------------------------------------------------
// Prep kernel: blocks [0,4096) convert q,k fp32->fp16; blocks [4096,4608)
// transpose+convert the 4 weight matrices into [n][k] fp16.
// ---------------------------------------------------------------------------
#define QK_ELEMS (NROWS * DIN)   // 8.4M
#define CVT_BLOCKS (QK_ELEMS / 2048)   // 4096

__global__ void prep_kernel(
    const float* __restrict__ q,  const float* __restrict__ k, __half* __restrict__ X,
    const float* __restrict__ Wa1, const float* __restrict__ Wb1,
    const float* __restrict__ Wa2, const float* __restrict__ Wb2,
    __half* __restrict__ T1a, __half* __restrict__ T1b,
    __half* __restrict__ T2a, __half* __restrict__ T2b)
{
    int tid = threadIdx.x;
    if (blockIdx.x < CVT_BLOCKS) {
        long i = ((long)blockIdx.x * 256 + tid) * 8;
        const long half_pt = (long)(NROWS / 2) * DIN;
        const float* src = (i < half_pt) ? q + i : k + (i - half_pt);
        float4 v0 = *(const float4*)(src);
        float4 v1 = *(const float4*)(src + 4);
        __half2 h[4];
        h[0] = __floats2half2_rn(v0.x, v0.y);
        h[1] = __floats2half2_rn(v0.z, v0.w);
        h[2] = __floats2half2_rn(v1.x, v1.y);
        h[3] = __floats2half2_rn(v1.z, v1.w);
        *(uint4*)(X + i) = *(uint4*)h;
        return;
    }
    __shared__ float t[32][33];
    int idx = blockIdx.x - CVT_BLOCKS;    // [0, 512)
    int z  = idx >> 7;
    int rem = idx & 127;
    int gy = rem >> 4, gx = rem & 15;
    int K = (z < 2) ? DIN : DOUT;
    if (gx * 32 >= K) return;
    const float* S = (z == 0) ? Wa1 : (z == 1) ? Wb1 : (z == 2) ? Wa2 : Wb2;
    __half*      D = (z == 0) ? T1a : (z == 1) ? T1b : (z == 2) ? T2a : T2b;

    int kb = gx * 32, nb = gy * 32;
    int x = tid & 31, y = tid >> 5;  // 32 x 8
#pragma unroll
    for (int i = 0; i < 32; i += 8)
        t[y + i][x] = S[(long)(kb + y + i) * DOUT + nb + x];
    __syncthreads();
#pragma unroll
    for (int i = 0; i < 32; i += 8)
        D[(long)(nb + y + i) * K + kb + x] = __float2half(t[x][y + i]);
}

// ---------------------------------------------------------------------------
// fp16 MLP GEMM, cp.async 4-stage, BK=32 halfs, ldmatrix + mma.m16n8k16.
// C[16384,256] = fp16(relu(X @ W + bias)), dual weight set, W transposed.
// grid = (4, 128): x = set*2 + colblock(128). Block tile 128x128.
// 8 warps as 2(m)x4(n), warp tile 64x32. smem rows 80B (20 u32).
// ---------------------------------------------------------------------------
#define MLPH_TILE_U32 2560    // 128 rows x 20 u32
#define MLPH_SMEM_BYTES (4 * 2 * MLPH_TILE_U32 * 4)   // 81920

__global__ void __launch_bounds__(256, 2) mlp_f16_kernel(
    const __half* __restrict__ X1, const __half* __restrict__ Wt1,
    const float* __restrict__ bias1, __half* __restrict__ C1,
    const __half* __restrict__ X2, const __half* __restrict__ Wt2,
    const float* __restrict__ bias2, __half* __restrict__ C2,
    int K)
{
    extern __shared__ unsigned sm[];
    unsigned* ASb = sm;                        // 4 x 2560
    unsigned* BSb = sm + 4 * MLPH_TILE_U32;    // 4 x 2560

    int set = blockIdx.x >> 1;
    int bn  = blockIdx.x & 1;
    long rbase = (long)blockIdx.y * 128;

    const __half* X    = (set ? X2 : X1) + rbase * K;
    const __half* Wb   = (set ? Wt2 : Wt1) + (long)(bn * 128) * K;
    const float*  bias = set ? bias2 : bias1;
    __half*       C    = set ? C2  : C1;

    int tid = threadIdx.x;
    int wid = tid >> 5, lane = tid & 31;
    int wm  = wid >> 2, wn = wid & 3;          // 2(m) x 4(n)
    int g   = lane >> 2, t4 = lane & 3;

    int r0 = tid >> 2,          c0 = tid & 3;
    int r1 = (tid + 256) >> 2,  c1 = (tid + 256) & 3;

    int l7 = lane & 7, l8 = (lane >> 3) & 1, l16 = (lane >> 4) & 1;
    unsigned aoff = (unsigned)((wm * 64 + l7 + l8 * 8) * 80 + l16 * 16);  // +mt*1280
    unsigned boff = (unsigned)((wn * 32 + l7 + l16 * 8) * 80 + l8 * 16);  // +ntp*1280
    unsigned aBase = (unsigned)__cvta_generic_to_shared(ASb);
    unsigned bBase = (unsigned)__cvta_generic_to_shared(BSb);

    float acc[4][4][4];
#pragma unroll
    for (int mt = 0; mt < 4; mt++)
#pragma unroll
        for (int nt = 0; nt < 4; nt++)
#pragma unroll
            for (int c = 0; c < 4; c++) acc[mt][nt][c] = 0.f;

    const int ITERS = K >> 5;

#define MLP_ISSUE(ki) do {                                                    \
        int st_ = (ki) & 3; int k0_ = (ki) << 5;                              \
        unsigned* A_ = ASb + st_ * MLPH_TILE_U32;                             \
        unsigned* B_ = BSb + st_ * MLPH_TILE_U32;                             \
        cp16(A_ + r0 * 20 + c0 * 4, X  + (long)r0 * K + k0_ + c0 * 8);        \
        cp16(A_ + r1 * 20 + c1 * 4, X  + (long)r1 * K + k0_ + c1 * 8);        \
        cp16(B_ + r0 * 20 + c0 * 4, Wb + (long)r0 * K + k0_ + c0 * 8);        \
        cp16(B_ + r1 * 20 + c1 * 4, Wb + (long)r1 * K + k0_ + c1 * 8);        \
    } while (0)

    MLP_ISSUE(0); cp_commit();
    MLP_ISSUE(1); cp_commit();
    MLP_ISSUE(2); cp_commit();

    for (int it = 0; it < ITERS; it++) {
        cp_wait<2>();
        __syncthreads();
        if (it + 3 < ITERS) MLP_ISSUE(it + 3);
        cp_commit();

        int st = it & 3;
        unsigned aS = aBase + st * (MLPH_TILE_U32 * 4);
        unsigned bS = bBase + st * (MLPH_TILE_U32 * 4);

#pragma unroll
        for (int k16 = 0; k16 < 2; k16++) {
            unsigned kbyt = k16 * 32;
            unsigned af[4][4], bf[2][4];
#pragma unroll
            for (int mt = 0; mt < 4; mt++)
                ldsm_x4(af[mt][0], af[mt][1], af[mt][2], af[mt][3],
                        aS + aoff + mt * 1280 + kbyt);
#pragma unroll
            for (int ntp = 0; ntp < 2; ntp++)
                ldsm_x4(bf[ntp][0], bf[ntp][1], bf[ntp][2], bf[ntp][3],
                        bS + boff + ntp * 1280 + kbyt);
#pragma unroll
            for (int nt = 0; nt < 4; nt++) {
                unsigned b0 = bf[nt >> 1][(nt & 1) * 2];
                unsigned b1 = bf[nt >> 1][(nt & 1) * 2 + 1];
#pragma unroll
                for (int mt = 0; mt < 4; mt++)
                    mma_f16(acc[mt][nt][0], acc[mt][nt][1],
                            acc[mt][nt][2], acc[mt][nt][3],
                            af[mt][0], af[mt][1], af[mt][2], af[mt][3],
                            b0, b1);
            }
        }
    }

    // epilogue: bias + relu, fp16 out
#pragma unroll
    for (int mt = 0; mt < 4; mt++) {
#pragma unroll
        for (int rr = 0; rr < 2; rr++) {
            long row = rbase + wm * 64 + mt * 16 + g + rr * 8;
#pragma unroll
            for (int nt = 0; nt < 4; nt++) {
                int col = bn * 128 + wn * 32 + nt * 8 + t4 * 2;
                float ox = fmaxf(acc[mt][nt][rr*2+0] + bias[col    ], 0.f);
                float oy = fmaxf(acc[mt][nt][rr*2+1] + bias[col + 1], 0.f);
                *(__half2*)(C + row * DOUT + col) = __floats2half2_rn(ox, oy);
            }
        }
    }
}

// ---------------------------------------------------------------------------
// fp16 fused score GEMM (a & b) + HardKuma epilogue, cp.async 3-stage,
// ldmatrix + mma.m16n8k16. grid = (32, 16, 4): tile 128(t) x 64(s),
// BK=32 halfs, K=256 -> 8 iters. 256 threads, 2 blocks/SM. (R11 config —
// best measured attn shape.)
// ---------------------------------------------------------------------------
#define Q_TILE_U32 2560   // 128 rows x 20 u32
#define K_TILE_U32 1280   // 64 rows x 20 u32
#define ATTN_SMEM_BYTES (3 * (2 * Q_TILE_U32 + 2 * K_TILE_U32) * 4)

__global__ void __launch_bounds__(256, 2) kuma_attn_f16_kernel(
    const unsigned short* __restrict__ Au, const unsigned short* __restrict__ Bu,
    const float* __restrict__ dist_emb, float* __restrict__ out)
{
    extern __shared__ unsigned sm[];
    unsigned* QAb = sm;
    unsigned* QBb = sm + 3 * Q_TILE_U32;
    unsigned* KAb = sm + 6 * Q_TILE_U32;
    unsigned* KBb = sm + 6 * Q_TILE_U32 + 3 * K_TILE_U32;
    __shared__ float sdist[23];

    const __half* Ah = (const __half*)Au;
    const __half* Bh = (const __half*)Bu;

    int b  = blockIdx.z;
    int bt = blockIdx.y * 128;
    int bs = blockIdx.x * 64;
    int tid = threadIdx.x;
    if (tid < 23) sdist[tid] = dist_emb[tid];

    int wid = tid >> 5, lane = tid & 31;
    int wm  = wid >> 1, wn = wid & 1;
    int g   = lane >> 2, t4 = lane & 3;

    const __half* qa = Ah + ((long)b * T_SEQ + bt) * DOUT;
    const __half* ka = Ah + ((long)(8192 + b * T_SEQ) + bs) * DOUT;
    const __half* qb = Bh + ((long)b * T_SEQ + bt) * DOUT;
    const __half* kb = Bh + ((long)(8192 + b * T_SEQ) + bs) * DOUT;

    int rQ0 = tid >> 2,         cQ0 = (tid & 3);
    int rQ1 = (tid + 256) >> 2, cQ1 = ((tid + 256) & 3);
    int rK = tid >> 2,          cK  = (tid & 3);

    int l7 = lane & 7, l8 = (lane >> 3) & 1, l16 = (lane >> 4) & 1;
    unsigned aoff = (unsigned)((wm * 32 + l7 + l8 * 8) * 80 + l16 * 16);
    unsigned boff = (unsigned)((wn * 32 + l7 + l16 * 8) * 80 + l8 * 16);
    unsigned qaB = (unsigned)__cvta_generic_to_shared(QAb);
    unsigned qbB = (unsigned)__cvta_generic_to_shared(QBb);
    unsigned kaB = (unsigned)__cvta_generic_to_shared(KAb);
    unsigned kbB = (unsigned)__cvta_generic_to_shared(KBb);

    float accA[2][4][4], accB[2][4][4];
#pragma unroll
    for (int mt = 0; mt < 2; mt++)
#pragma unroll
        for (int nt = 0; nt < 4; nt++)
#pragma unroll
            for (int c = 0; c < 4; c++) { accA[mt][nt][c] = 0.f; accB[mt][nt][c] = 0.f; }

    const int ITERS = DOUT >> 5;   // 8

#define ATTN_ISSUE(ki) do {                                                   \
        int st_ = (ki) % 3; int k0_ = (ki) << 5;                              \
        unsigned* QA_ = QAb + st_ * Q_TILE_U32;                               \
        unsigned* QB_ = QBb + st_ * Q_TILE_U32;                               \
        unsigned* KA_ = KAb + st_ * K_TILE_U32;                               \
        unsigned* KB_ = KBb + st_ * K_TILE_U32;                               \
        cp16(QA_ + rQ0 * 20 + cQ0 * 4, qa + (long)rQ0 * DOUT + k0_ + cQ0 * 8);\
        cp16(QA_ + rQ1 * 20 + cQ1 * 4, qa + (long)rQ1 * DOUT + k0_ + cQ1 * 8);\
        cp16(QB_ + rQ0 * 20 + cQ0 * 4, qb + (long)rQ0 * DOUT + k0_ + cQ0 * 8);\
        cp16(QB_ + rQ1 * 20 + cQ1 * 4, qb + (long)rQ1 * DOUT + k0_ + cQ1 * 8);\
        cp16(KA_ + rK * 20 + cK * 4, ka + (long)rK * DOUT + k0_ + cK * 8);    \
        cp16(KB_ + rK * 20 + cK * 4, kb + (long)rK * DOUT + k0_ + cK * 8);    \
    } while (0)

    ATTN_ISSUE(0); cp_commit();
    ATTN_ISSUE(1); cp_commit();

    for (int it = 0; it < ITERS; it++) {
        cp_wait<1>();
        __syncthreads();
        if (it + 2 < ITERS) ATTN_ISSUE(it + 2);
        cp_commit();

        int st = it % 3;
        unsigned qaS = qaB + st * (Q_TILE_U32 * 4);
        unsigned qbS = qbB + st * (Q_TILE_U32 * 4);
        unsigned kaS = kaB + st * (K_TILE_U32 * 4);
        unsigned kbS = kbB + st * (K_TILE_U32 * 4);

#pragma unroll
        for (int k16 = 0; k16 < 2; k16++) {
            unsigned kbyt = k16 * 32;
            unsigned qaf[2][4], qbf[2][4], kaf[2][4], kbf[2][4];
#pragma unroll
            for (int mt = 0; mt < 2; mt++) {
                ldsm_x4(qaf[mt][0], qaf[mt][1], qaf[mt][2], qaf[mt][3],
                        qaS + aoff + mt * 1280 + kbyt);
                ldsm_x4(qbf[mt][0], qbf[mt][1], qbf[mt][2], qbf[mt][3],
                        qbS + aoff + mt * 1280 + kbyt);
            }
#pragma unroll
            for (int ntp = 0; ntp < 2; ntp++) {
                ldsm_x4(kaf[ntp][0], kaf[ntp][1], kaf[ntp][2], kaf[ntp][3],
                        kaS + boff + ntp * 1280 + kbyt);
                ldsm_x4(kbf[ntp][0], kbf[ntp][1], kbf[ntp][2], kbf[ntp][3],
                        kbS + boff + ntp * 1280 + kbyt);
            }
#pragma unroll
            for (int nt = 0; nt < 4; nt++) {
                unsigned bA0 = kaf[nt >> 1][(nt & 1) * 2];
                unsigned bA1 = kaf[nt >> 1][(nt & 1) * 2 + 1];
                unsigned bB0 = kbf[nt >> 1][(nt & 1) * 2];
                unsigned bB1 = kbf[nt >> 1][(nt & 1) * 2 + 1];
#pragma unroll
                for (int mt = 0; mt < 2; mt++) {
                    mma_f16(accA[mt][nt][0], accA[mt][nt][1],
                            accA[mt][nt][2], accA[mt][nt][3],
                            qaf[mt][0], qaf[mt][1], qaf[mt][2], qaf[mt][3],
                            bA0, bA1);
                    mma_f16(accB[mt][nt][0], accB[mt][nt][1],
                            accB[mt][nt][2], accB[mt][nt][3],
                            qbf[mt][0], qbf[mt][1], qbf[mt][2], qbf[mt][3],
                            bB0, bB1);
                }
            }
        }
    }

    // HardKuma epilogue + store
#pragma unroll
    for (int mt = 0; mt < 2; mt++) {
#pragma unroll
        for (int rr = 0; rr < 2; rr++) {
            int trow = bt + wm * 32 + mt * 16 + g + rr * 8;
#pragma unroll
            for (int nt = 0; nt < 4; nt++) {
                int scol = bs + wn * 32 + nt * 8 + t4 * 2;
                int rel0 = max(-11, min(11, scol     - trow)) + 11;
                int rel1 = max(-11, min(11, scol + 1 - trow)) + 11;
                float rd0 = sdist[rel0], rd1 = sdist[rel1];
                float2 o;
                o.x = kuma_out(accA[mt][nt][rr*2+0] + rd0, accB[mt][nt][rr*2+0] + rd0);
                o.y = kuma_out(accA[mt][nt][rr*2+1] + rd1, accB[mt][nt][rr*2+1] + rd1);
                *(float2*)(out + ((long)b * T_SEQ + trow) * T_SEQ + scol) = o;
            }
        }
    }
}

// ---------------------------------------------------------------------------
extern "C" void kernel_launch(void* const* d_in, const int* in_sizes, int n_in,
                              void* d_out, int out_size)
{
    const float* q    = (const float*)d_in[0];
    const float* k    = (const float*)d_in[1];
    const float* Wa1  = (const float*)d_in[2];
    const float* ba1  = (const float*)d_in[3];
    const float* Wa2  = (const float*)d_in[4];
    const float* ba2  = (const float*)d_in[5];
    const float* Wb1  = (const float*)d_in[6];
    const float* bb1  = (const float*)d_in[7];
    const float* Wb2  = (const float*)d_in[8];
    const float* bb2  = (const float*)d_in[9];
    const float* dist = (const float*)d_in[10];
    float* out = (float*)d_out;

    unsigned short *X16, *h1, *h2, *Ah, *Bh, *t1a, *t1b, *t2a, *t2b;
    cudaGetSymbolAddress((void**)&X16, g_X16);
    cudaGetSymbolAddress((void**)&h1,  g_h1);
    cudaGetSymbolAddress((void**)&h2,  g_h2);
    cudaGetSymbolAddress((void**)&Ah,  g_A);
    cudaGetSymbolAddress((void**)&Bh,  g_B);
    cudaGetSymbolAddress((void**)&t1a, g_Wt1a);
    cudaGetSymbolAddress((void**)&t1b, g_Wt1b);
    cudaGetSymbolAddress((void**)&t2a, g_Wt2a);
    cudaGetSymbolAddress((void**)&t2b, g_Wt2b);

    cudaFuncSetAttribute(mlp_f16_kernel,
        cudaFuncAttributeMaxDynamicSharedMemorySize, MLPH_SMEM_BYTES);
    cudaFuncSetAttribute(kuma_attn_f16_kernel,
        cudaFuncAttributeMaxDynamicSharedMemorySize, ATTN_SMEM_BYTES);

    prep_kernel<<<CVT_BLOCKS + 512, 256>>>(
        q, k, (__half*)X16,
        Wa1, Wb1, Wa2, Wb2,
        (__half*)t1a, (__half*)t1b, (__half*)t2a, (__half*)t2b);

    dim3 g1(4, 128);
    mlp_f16_kernel<<<g1, 256, MLPH_SMEM_BYTES>>>(
        (const __half*)X16, (const __half*)t1a, ba1, (__half*)h1,
        (const __half*)X16, (const __half*)t1b, bb1, (__half*)h2, DIN);
    mlp_f16_kernel<<<g1, 256, MLPH_SMEM_BYTES>>>(
        (const __half*)h1, (const __half*)t2a, ba2, (__half*)Ah,
        (const __half*)h2, (const __half*)t2b, bb2, (__half*)Bh, DOUT);

    dim3 g2(T_SEQ / 64, T_SEQ / 128, BATCH);
    kuma_attn_f16_kernel<<<g2, 256, ATTN_SMEM_BYTES>>>(Ah, Bh, dist, out);
}